// round 1
// baseline (speedup 1.0000x reference)
#include <cuda_runtime.h>
#include <cuda_bf16.h>
#include <cstdint>

// DifferentiableNLMS: B=32, T=2000, F=513, L=32, mu=0.1, eps=1e-8
// One thread per (b,f) pair. W and the X window live in registers.
// Time loop unrolled by 32 so the ring-buffer indices are compile-time
// constants (window == entire ring each step -> no shifting).

#define NB 32
#define NT 2000
#define NF 513
#define NL 32
#define MU 0.1f
#define EPSV 1e-8f

#define NPAIR (NB * NF)          // 16416
#define TMAIN (NT / 32)          // 62 full blocks of 32
#define TTAIL (NT - TMAIN * 32)  // 16

template <int NS>
__device__ __forceinline__ void run_block(
    float (&W)[NL], float (&R)[NL],
    const float* __restrict__ xp, const float* __restrict__ yp,
    float* __restrict__ ep, int t)
{
    // Batch-prefetch all NS x/y samples for this block of steps.
    float xb[NS], yb[NS];
#pragma unroll
    for (int u = 0; u < NS; u++) {
        xb[u] = __ldg(xp + (size_t)(t + u) * NF);
        yb[u] = __ldg(yp + (size_t)(t + u) * NF);
    }

#pragma unroll
    for (int u = 0; u < NS; u++) {
        // step k = t + u, with t a multiple of 32 -> ring phase == u.
        // Insert newest sample: R[k & 31] = X[k]  (this is Xw[31]).
        R[u & 31] = xb[u];

        // Xw[j] = R[(u+1+j) & 31], j = 0..31  (covers the whole ring).
        float a0 = 0.f, a1 = 0.f, a2 = 0.f, a3 = 0.f;        // dot partials
        float n0 = EPSV, n1 = 0.f, n2 = 0.f, n3 = 0.f;       // norm partials (+eps)
#pragma unroll
        for (int j = 0; j < NL; j += 4) {
            float r0 = R[(u + 1 + j) & 31];
            float r1 = R[(u + 2 + j) & 31];
            float r2 = R[(u + 3 + j) & 31];
            float r3 = R[(u + 4 + j) & 31];
            a0 = fmaf(W[j + 0], r0, a0);
            a1 = fmaf(W[j + 1], r1, a1);
            a2 = fmaf(W[j + 2], r2, a2);
            a3 = fmaf(W[j + 3], r3, a3);
            n0 = fmaf(r0, r0, n0);
            n1 = fmaf(r1, r1, n1);
            n2 = fmaf(r2, r2, n2);
            n3 = fmaf(r3, r3, n3);
        }
        float y_hat = (a0 + a1) + (a2 + a3);
        float norm  = (n0 + n1) + (n2 + n3);
        float e = yb[u] - y_hat;

        ep[(size_t)(t + u) * NF] = e;

        float c = MU * __fdividef(e, norm);
#pragma unroll
        for (int j = 0; j < NL; j++) {
            W[j] = fmaf(c, R[(u + 1 + j) & 31], W[j]);
        }
    }
}

__global__ void __launch_bounds__(128)
nlms_kernel(const float* __restrict__ X, const float* __restrict__ Y,
            const float* __restrict__ Wp, float* __restrict__ out,
            int write_w)
{
    int p = blockIdx.x * blockDim.x + threadIdx.x;
    if (p >= NPAIR) return;
    int b = p / NF;
    int f = p - b * NF;

    size_t base = (size_t)b * NT * NF + f;
    const float* xp = X + base;
    const float* yp = Y + base;
    float* ep = out + base;  // E_hat_mag at offset 0

    float W[NL], R[NL];
#pragma unroll
    for (int j = 0; j < NL; j++) {
        W[j] = Wp[((size_t)b * NL + j) * NF + f];
        R[j] = 0.f;  // zero padding: window starts empty, matches ref pad
    }

    int t = 0;
    for (int blk = 0; blk < TMAIN; blk++) {
        run_block<32>(W, R, xp, yp, ep, t);
        t += 32;
    }
    run_block<TTAIL>(W, R, xp, yp, ep, t);

    if (write_w) {
        float* wf = out + (size_t)NB * NT * NF;  // W_final after E
#pragma unroll
        for (int j = 0; j < NL; j++) {
            wf[((size_t)b * NL + j) * NF + f] = W[j];
        }
    }
}

extern "C" void kernel_launch(void* const* d_in, const int* in_sizes, int n_in,
                              void* d_out, int out_size)
{
    const float* X  = (const float*)d_in[0];  // X_hat_mag [B,T,F]
    const float* Y  = (const float*)d_in[1];  // Y_mag     [B,T,F]
    const float* Wp = (const float*)d_in[2];  // W_prev    [B,L,F]
    float* out = (float*)d_out;

    // E is B*T*F; W_final is B*L*F. Write W_final only if out buffer holds both.
    long long need = (long long)NB * NT * NF + (long long)NB * NL * NF;
    int write_w = ((long long)out_size >= need) ? 1 : 0;

    // 16416 threads; grid padded to >=148 blocks (low-grid I$ throttle guard).
    int block = 128;
    int grid = 160;  // >= ceil(16416/128)=129 and >= 148
    nlms_kernel<<<grid, block>>>(X, Y, Wp, out, write_w);
}

// round 2
// speedup vs baseline: 1.0002x; 1.0002x over previous
#include <cuda_runtime.h>
#include <cuda_bf16.h>
#include <cstdint>

// DifferentiableNLMS: B=32, T=2000, F=513, L=32, mu=0.1, eps=1e-8
// One thread per (b,f) pair. W and the X window live in registers.
// Time loop unrolled by 32 so the ring-buffer indices are compile-time
// constants (window == entire ring each step -> no shifting).

#define NB 32
#define NT 2000
#define NF 513
#define NL 32
#define MU 0.1f
#define EPSV 1e-8f

#define NPAIR (NB * NF)          // 16416
#define TMAIN (NT / 32)          // 62 full blocks of 32
#define TTAIL (NT - TMAIN * 32)  // 16

template <int NS>
__device__ __forceinline__ void run_block(
    float (&W)[NL], float (&R)[NL],
    const float* __restrict__ xp, const float* __restrict__ yp,
    float* __restrict__ ep, int t)
{
    // Batch-prefetch all NS x/y samples for this block of steps.
    float xb[NS], yb[NS];
#pragma unroll
    for (int u = 0; u < NS; u++) {
        xb[u] = __ldg(xp + (size_t)(t + u) * NF);
        yb[u] = __ldg(yp + (size_t)(t + u) * NF);
    }

#pragma unroll
    for (int u = 0; u < NS; u++) {
        // step k = t + u, with t a multiple of 32 -> ring phase == u.
        // Insert newest sample: R[k & 31] = X[k]  (this is Xw[31]).
        R[u & 31] = xb[u];

        // Xw[j] = R[(u+1+j) & 31], j = 0..31  (covers the whole ring).
        float a0 = 0.f, a1 = 0.f, a2 = 0.f, a3 = 0.f;        // dot partials
        float n0 = EPSV, n1 = 0.f, n2 = 0.f, n3 = 0.f;       // norm partials (+eps)
#pragma unroll
        for (int j = 0; j < NL; j += 4) {
            float r0 = R[(u + 1 + j) & 31];
            float r1 = R[(u + 2 + j) & 31];
            float r2 = R[(u + 3 + j) & 31];
            float r3 = R[(u + 4 + j) & 31];
            a0 = fmaf(W[j + 0], r0, a0);
            a1 = fmaf(W[j + 1], r1, a1);
            a2 = fmaf(W[j + 2], r2, a2);
            a3 = fmaf(W[j + 3], r3, a3);
            n0 = fmaf(r0, r0, n0);
            n1 = fmaf(r1, r1, n1);
            n2 = fmaf(r2, r2, n2);
            n3 = fmaf(r3, r3, n3);
        }
        float y_hat = (a0 + a1) + (a2 + a3);
        float norm  = (n0 + n1) + (n2 + n3);
        float e = yb[u] - y_hat;

        ep[(size_t)(t + u) * NF] = e;

        float c = MU * __fdividef(e, norm);
#pragma unroll
        for (int j = 0; j < NL; j++) {
            W[j] = fmaf(c, R[(u + 1 + j) & 31], W[j]);
        }
    }
}

__global__ void __launch_bounds__(128)
nlms_kernel(const float* __restrict__ X, const float* __restrict__ Y,
            const float* __restrict__ Wp, float* __restrict__ out,
            int write_w)
{
    int p = blockIdx.x * blockDim.x + threadIdx.x;
    if (p >= NPAIR) return;
    int b = p / NF;
    int f = p - b * NF;

    size_t base = (size_t)b * NT * NF + f;
    const float* xp = X + base;
    const float* yp = Y + base;
    float* ep = out + base;  // E_hat_mag at offset 0

    float W[NL], R[NL];
#pragma unroll
    for (int j = 0; j < NL; j++) {
        W[j] = Wp[((size_t)b * NL + j) * NF + f];
        R[j] = 0.f;  // zero padding: window starts empty, matches ref pad
    }

    int t = 0;
    for (int blk = 0; blk < TMAIN; blk++) {
        run_block<32>(W, R, xp, yp, ep, t);
        t += 32;
    }
    run_block<TTAIL>(W, R, xp, yp, ep, t);

    if (write_w) {
        float* wf = out + (size_t)NB * NT * NF;  // W_final after E
#pragma unroll
        for (int j = 0; j < NL; j++) {
            wf[((size_t)b * NL + j) * NF + f] = W[j];
        }
    }
}

extern "C" void kernel_launch(void* const* d_in, const int* in_sizes, int n_in,
                              void* d_out, int out_size)
{
    const float* X  = (const float*)d_in[0];  // X_hat_mag [B,T,F]
    const float* Y  = (const float*)d_in[1];  // Y_mag     [B,T,F]
    const float* Wp = (const float*)d_in[2];  // W_prev    [B,L,F]
    float* out = (float*)d_out;

    // E is B*T*F; W_final is B*L*F. Write W_final only if out buffer holds both.
    long long need = (long long)NB * NT * NF + (long long)NB * NL * NF;
    int write_w = ((long long)out_size >= need) ? 1 : 0;

    // 16416 threads; grid padded to >=148 blocks (low-grid I$ throttle guard).
    int block = 128;
    int grid = 160;  // >= ceil(16416/128)=129 and >= 148
    nlms_kernel<<<grid, block>>>(X, Y, Wp, out, write_w);
}

// round 3
// speedup vs baseline: 1.0482x; 1.0480x over previous
#include <cuda_runtime.h>
#include <cuda_bf16.h>
#include <cstdint>

// DifferentiableNLMS: B=32, T=2000, F=513, L=32, mu=0.1, eps=1e-8
// One thread per (b,f). W and the 32-sample X window live in registers,
// time loop unrolled by 32 so ring indices are compile-time constants.
//
// R3 changes vs R1:
//  - incremental running norm S (2 FMA/step instead of 32)
//  - per-block precompute of minv[u] = MU/(S_u+eps): all MUFU.RCP latency
//    is pulled off the serial dot->update critical path
//  - 8 dot accumulators (chain depth 4)

#define NB 32
#define NT 2000
#define NF 513
#define NL 32
#define MU 0.1f
#define EPSV 1e-8f

#define NPAIR (NB * NF)          // 16416
#define TMAIN (NT / 32)          // 62 full blocks of 32
#define TTAIL (NT - TMAIN * 32)  // 16

template <int NS>
__device__ __forceinline__ void run_block(
    float (&W)[NL], float (&R)[NL], float& S,
    const float* __restrict__ xp, const float* __restrict__ yp,
    float* __restrict__ ep, int t)
{
    // Batch-prefetch all NS x/y samples for this block (MLP = 2*NS).
    float xb[NS], yb[NS];
#pragma unroll
    for (int u = 0; u < NS; u++) {
        xb[u] = __ldg(xp + (size_t)(t + u) * NF);
        yb[u] = __ldg(yp + (size_t)(t + u) * NF);
    }

    // Precompute step-size/norm for every step of this block.
    // S_u = sum of squares of window at step u; window at step u drops
    // R[u&31] (the sample from 32 steps ago, still unmodified here) and
    // gains xb[u]. All reciprocals are independent of the W recursion.
    float minv[NS];
#pragma unroll
    for (int u = 0; u < NS; u++) {
        float old = R[u & 31];
        S = fmaf(xb[u], xb[u], S);
        S = fmaf(-old, old, S);
        minv[u] = __fdividef(MU, S + EPSV);
    }

    // Serial NLMS recursion.
#pragma unroll
    for (int u = 0; u < NS; u++) {
        // step k = t + u, t multiple of 32 -> ring phase == u.
        R[u & 31] = xb[u];  // newest sample = Xw[31]

        // Xw[j] = R[(u+1+j) & 31], j = 0..31 (whole ring).
        float a0 = 0.f, a1 = 0.f, a2 = 0.f, a3 = 0.f;
        float a4 = 0.f, a5 = 0.f, a6 = 0.f, a7 = 0.f;
#pragma unroll
        for (int j = 0; j < NL; j += 8) {
            a0 = fmaf(W[j + 0], R[(u + 1 + j) & 31], a0);
            a1 = fmaf(W[j + 1], R[(u + 2 + j) & 31], a1);
            a2 = fmaf(W[j + 2], R[(u + 3 + j) & 31], a2);
            a3 = fmaf(W[j + 3], R[(u + 4 + j) & 31], a3);
            a4 = fmaf(W[j + 4], R[(u + 5 + j) & 31], a4);
            a5 = fmaf(W[j + 5], R[(u + 6 + j) & 31], a5);
            a6 = fmaf(W[j + 6], R[(u + 7 + j) & 31], a6);
            a7 = fmaf(W[j + 7], R[(u + 8 + j) & 31], a7);
        }
        float y_hat = ((a0 + a1) + (a2 + a3)) + ((a4 + a5) + (a6 + a7));
        float e = yb[u] - y_hat;

        ep[(size_t)(t + u) * NF] = e;

        float c = e * minv[u];
#pragma unroll
        for (int j = 0; j < NL; j++) {
            W[j] = fmaf(c, R[(u + 1 + j) & 31], W[j]);
        }
    }
}

__global__ void __launch_bounds__(128)
nlms_kernel(const float* __restrict__ X, const float* __restrict__ Y,
            const float* __restrict__ Wp, float* __restrict__ out,
            int write_w)
{
    int p = blockIdx.x * blockDim.x + threadIdx.x;
    if (p >= NPAIR) return;
    int b = p / NF;
    int f = p - b * NF;

    size_t base = (size_t)b * NT * NF + f;
    const float* xp = X + base;
    const float* yp = Y + base;
    float* ep = out + base;  // E_hat_mag at offset 0

    float W[NL], R[NL];
#pragma unroll
    for (int j = 0; j < NL; j++) {
        W[j] = Wp[((size_t)b * NL + j) * NF + f];
        R[j] = 0.f;  // zero-pad: window starts empty (matches ref front-pad)
    }
    float S = 0.f;  // running sum of squares of the ring

    int t = 0;
    for (int blk = 0; blk < TMAIN; blk++) {
        run_block<32>(W, R, S, xp, yp, ep, t);
        t += 32;
    }
    run_block<TTAIL>(W, R, S, xp, yp, ep, t);

    if (write_w) {
        float* wf = out + (size_t)NB * NT * NF;  // W_final after E
#pragma unroll
        for (int j = 0; j < NL; j++) {
            wf[((size_t)b * NL + j) * NF + f] = W[j];
        }
    }
}

extern "C" void kernel_launch(void* const* d_in, const int* in_sizes, int n_in,
                              void* d_out, int out_size)
{
    const float* X  = (const float*)d_in[0];  // X_hat_mag [B,T,F]
    const float* Y  = (const float*)d_in[1];  // Y_mag     [B,T,F]
    const float* Wp = (const float*)d_in[2];  // W_prev    [B,L,F]
    float* out = (float*)d_out;

    long long need = (long long)NB * NT * NF + (long long)NB * NL * NF;
    int write_w = ((long long)out_size >= need) ? 1 : 0;

    // 16416 threads; 129 worker blocks, padded to 160 (idle blocks exit
    // immediately; workers all land in wave 1, one per SM).
    nlms_kernel<<<160, 128>>>(X, Y, Wp, out, write_w);
}

// round 4
// speedup vs baseline: 1.6101x; 1.5361x over previous
#include <cuda_runtime.h>
#include <cuda_bf16.h>
#include <cstdint>

// DifferentiableNLMS: B=32, T=2000, F=513, L=32, mu=0.1, eps=1e-8
// One thread per (b,f). Two-step lookahead NLMS with packed f32x2 FMAs:
//   e_{t+1} = (y_{t+1} - W_t.Xw_{t+1}) - c_t * (Xw_t.Xw_{t+1})
// Window kept as two phase-shifted packed rings (P: (x_odd,x_even),
// Q: (x_even,x_odd)); per 2 steps the window moves one pair slot, so all
// packing is alignment-stable and ring indices are compile-time constants.

#define NB 32
#define NT 2000
#define NF 513
#define NL 32
#define MU 0.1f
#define EPSV 1e-8f

#define NPAIR (NB * NF)     // 16416
#define NSTEP 16            // steps per block
#define NPB 8               // pairs per block
#define NDBL 62             // double-blocks; 62*2+1 = 125 = 2000/16

typedef unsigned long long u64;

__device__ __forceinline__ u64 ffma2(u64 a, u64 b, u64 c) {
    u64 d; asm("fma.rn.f32x2 %0, %1, %2, %3;" : "=l"(d) : "l"(a), "l"(b), "l"(c));
    return d;
}
__device__ __forceinline__ u64 fadd2(u64 a, u64 b) {
    u64 d; asm("add.rn.f32x2 %0, %1, %2;" : "=l"(d) : "l"(a), "l"(b));
    return d;
}
__device__ __forceinline__ u64 pack2(float lo, float hi) {
    u64 d; asm("mov.b64 %0, {%1, %2};" : "=l"(d) : "f"(lo), "f"(hi));
    return d;
}
__device__ __forceinline__ void unpack2(u64 v, float& lo, float& hi) {
    asm("mov.b64 {%0, %1}, %2;" : "=f"(lo), "=f"(hi) : "l"(v));
}

__device__ __forceinline__ void prefetch16(float (&x)[NSTEP], float (&y)[NSTEP],
                                           const float* __restrict__ xp,
                                           const float* __restrict__ yp, int t)
{
#pragma unroll
    for (int u = 0; u < NSTEP; u++) {
        x[u] = __ldg(xp + (size_t)(t + u) * NF);
        y[u] = __ldg(yp + (size_t)(t + u) * NF);
    }
}

// M0 = ring phase (t0/2 mod 16): 0 or 8 for NSTEP=16.
template <int M0>
__device__ __forceinline__ void run_block(
    u64 (&W2)[16], u64 (&P)[16], u64 (&Q)[16],
    float& S, float& CC, float& xlast,
    const float (&xb)[NSTEP], const float (&yb)[NSTEP],
    float* __restrict__ ep, int t0)
{
    float minv[NSTEP];
    float cc[NPB];
    float xm1_0 = xlast;

    // ---- Prologue: norms, cross-correlations, reciprocals ----
    // Reads OLD ring slots (drops) before any insertion; all independent of W,
    // so every MUFU.RCP sits off the serial recursion's critical path.
#pragma unroll
    for (int p = 0; p < NPB; p++) {
        const int m = (M0 + p) & 15;
        float a, b, bq, cq;
        unpack2(P[m], a, b);   // (x_{t-33}, x_{t-32})
        unpack2(Q[m], bq, cq); // (x_{t-32}, x_{t-31})
        float xm1 = (p == 0) ? xm1_0 : xb[2 * p - 1];
        float x0 = xb[2 * p], x1 = xb[2 * p + 1];
        S = fmaf(x0, x0, S);
        S = fmaf(-b, b, S);
        minv[2 * p] = __fdividef(MU, S + EPSV);
        S = fmaf(x1, x1, S);
        S = fmaf(-cq, cq, S);
        minv[2 * p + 1] = __fdividef(MU, S + EPSV);
        CC = fmaf(xm1, x0, CC);
        CC = fmaf(x0, x1, CC);
        CC = fmaf(-a, b, CC);
        CC = fmaf(-bq, cq, CC);
        cc[p] = CC;
    }
    xlast = xb[NSTEP - 1];

    // ---- Serial recursion, 2 steps per iteration, fully packed ----
#pragma unroll
    for (int p = 0; p < NPB; p++) {
        const int m = (M0 + p) & 15;
        float xm1 = (p == 0) ? xm1_0 : xb[2 * p - 1];
        float x0 = xb[2 * p], x1 = xb[2 * p + 1];
        P[m] = pack2(xm1, x0);  // slot t/2 = (x_{t-1}, x_t)
        Q[m] = pack2(x0, x1);   // slot t/2 = (x_t, x_{t+1})

        // p_t = W.Xw_t (P-phase), q_t = W.Xw_{t+1} (Q-phase): 32 FFMA2.
        u64 a0 = 0, a1 = 0, a2 = 0, a3 = 0;
        u64 b0 = 0, b1 = 0, b2 = 0, b3 = 0;
#pragma unroll
        for (int i = 0; i < 16; i += 4) {
            a0 = ffma2(W2[i + 0], P[(m + 1 + i) & 15], a0);
            a1 = ffma2(W2[i + 1], P[(m + 2 + i) & 15], a1);
            a2 = ffma2(W2[i + 2], P[(m + 3 + i) & 15], a2);
            a3 = ffma2(W2[i + 3], P[(m + 4 + i) & 15], a3);
            b0 = ffma2(W2[i + 0], Q[(m + 1 + i) & 15], b0);
            b1 = ffma2(W2[i + 1], Q[(m + 2 + i) & 15], b1);
            b2 = ffma2(W2[i + 2], Q[(m + 3 + i) & 15], b2);
            b3 = ffma2(W2[i + 3], Q[(m + 4 + i) & 15], b3);
        }
        u64 ap = fadd2(fadd2(a0, a1), fadd2(a2, a3));
        u64 aq = fadd2(fadd2(b0, b1), fadd2(b2, b3));
        float plo, phi, qlo, qhi;
        unpack2(ap, plo, phi);
        unpack2(aq, qlo, qhi);
        float pt = plo + phi;
        float qt = qlo + qhi;

        float e0 = yb[2 * p] - pt;
        float c0 = e0 * minv[2 * p];
        float e1 = fmaf(-c0, cc[p], yb[2 * p + 1] - qt);
        float c1 = e1 * minv[2 * p + 1];

        ep[(size_t)(t0 + 2 * p) * NF] = e0;
        ep[(size_t)(t0 + 2 * p + 1) * NF] = e1;

        u64 c0p = pack2(c0, c0);
        u64 c1p = pack2(c1, c1);
        // W += c0*Xw_t, then += c1*Xw_{t+1}: 32 FFMA2, same per-tap order
        // as the reference's two sequential updates.
#pragma unroll
        for (int i = 0; i < 16; i++) {
            W2[i] = ffma2(c1p, Q[(m + 1 + i) & 15],
                          ffma2(c0p, P[(m + 1 + i) & 15], W2[i]));
        }
    }
}

__global__ void __launch_bounds__(64, 1)
nlms_kernel(const float* __restrict__ X, const float* __restrict__ Y,
            const float* __restrict__ Wp, float* __restrict__ out,
            int write_w)
{
    int p = blockIdx.x * blockDim.x + threadIdx.x;
    if (p >= NPAIR) return;
    int b = p / NF;
    int f = p - b * NF;

    size_t base = (size_t)b * NT * NF + f;
    const float* xp = X + base;
    const float* yp = Y + base;
    float* ep = out + base;  // E_hat_mag at offset 0

    u64 W2[16], P[16], Q[16];
#pragma unroll
    for (int i = 0; i < 16; i++) {
        float w0 = Wp[((size_t)b * NL + 2 * i) * NF + f];
        float w1 = Wp[((size_t)b * NL + 2 * i + 1) * NF + f];
        W2[i] = pack2(w0, w1);
        P[i] = 0;  // zero pad: window starts empty
        Q[i] = 0;
    }
    float S = 0.f, CC = 0.f, xlast = 0.f;

    float xA[NSTEP], yA[NSTEP], xB[NSTEP], yB[NSTEP];
    prefetch16(xA, yA, xp, yp, 0);

    int t0 = 0;
    for (int bb = 0; bb < NDBL; bb++) {
        prefetch16(xB, yB, xp, yp, t0 + NSTEP);
        run_block<0>(W2, P, Q, S, CC, xlast, xA, yA, ep, t0);
        t0 += NSTEP;
        prefetch16(xA, yA, xp, yp, t0 + NSTEP);  // last iter lands on block 124
        run_block<8>(W2, P, Q, S, CC, xlast, xB, yB, ep, t0);
        t0 += NSTEP;
    }
    // final block 124 (t0 = 1984), phase (1984/16=124, 124*8 mod 16 = 0)
    run_block<0>(W2, P, Q, S, CC, xlast, xA, yA, ep, t0);

    if (write_w) {
        float* wf = out + (size_t)NB * NT * NF;  // W_final after E
#pragma unroll
        for (int i = 0; i < 16; i++) {
            float w0, w1;
            unpack2(W2[i], w0, w1);
            wf[((size_t)b * NL + 2 * i) * NF + f] = w0;
            wf[((size_t)b * NL + 2 * i + 1) * NF + f] = w1;
        }
    }
}

extern "C" void kernel_launch(void* const* d_in, const int* in_sizes, int n_in,
                              void* d_out, int out_size)
{
    const float* X  = (const float*)d_in[0];  // X_hat_mag [B,T,F]
    const float* Y  = (const float*)d_in[1];  // Y_mag     [B,T,F]
    const float* Wp = (const float*)d_in[2];  // W_prev    [B,L,F]
    float* out = (float*)d_out;

    long long need = (long long)NB * NT * NF + (long long)NB * NL * NF;
    int write_w = ((long long)out_size >= need) ? 1 : 0;

    // 16416 threads, 64/block -> 257 blocks (>=148, full first wave).
    nlms_kernel<<<257, 64>>>(X, Y, Wp, out, write_w);
}

// round 5
// speedup vs baseline: 1.9049x; 1.1831x over previous
#include <cuda_runtime.h>
#include <cuda_bf16.h>
#include <cstdint>

// DifferentiableNLMS: B=32, T=2000, F=513, L=32, mu=0.1, eps=1e-8
// Two threads per (b,f) sequence: thread h owns taps [16h, 16h+16) and runs
// on a time-shifted x stream (h=0 shifted by -16 frames; zero-pad makes this
// exact), so both threads execute identical code on an 8-pair (16-sample)
// ring with compile-time indices. Partial dots/norms/cross-correlations are
// summed with one lane-xor shuffle. Two-step lookahead + packed f32x2 FMAs.

#define NB 32
#define NT 2000
#define NF 513
#define NL 32
#define MU 0.1f
#define EPSV 1e-8f

#define NPAIR (NB * NF)        // 16416 sequences
#define NTHREAD (NPAIR * 2)    // 32832 threads = 1026 full warps
#define NSTEP 16               // steps per block (= one full ring revolution)
#define NPB 8                  // lookahead-pairs per block
#define NDBL 62                // 62*2+1 = 125 blocks = 2000/16

typedef unsigned long long u64;

__device__ __forceinline__ u64 ffma2(u64 a, u64 b, u64 c) {
    u64 d; asm("fma.rn.f32x2 %0, %1, %2, %3;" : "=l"(d) : "l"(a), "l"(b), "l"(c));
    return d;
}
__device__ __forceinline__ u64 fadd2(u64 a, u64 b) {
    u64 d; asm("add.rn.f32x2 %0, %1, %2;" : "=l"(d) : "l"(a), "l"(b));
    return d;
}
__device__ __forceinline__ u64 pack2(float lo, float hi) {
    u64 d; asm("mov.b64 %0, {%1, %2};" : "=l"(d) : "f"(lo), "f"(hi));
    return d;
}
__device__ __forceinline__ void unpack2(u64 v, float& lo, float& hi) {
    asm("mov.b64 {%0, %1}, %2;" : "=f"(lo), "=f"(hi) : "l"(v));
}
__device__ __forceinline__ u64 shfl64(u64 v) {
    return __shfl_xor_sync(0xFFFFFFFFu, v, 1);
}

// Guarded prefetch (first block only: h=0's shifted indices go negative -> 0).
__device__ __forceinline__ void prefetch_g(float (&x)[NSTEP], float (&y)[NSTEP],
                                           const float* __restrict__ xp,
                                           const float* __restrict__ yp,
                                           int t, int off)
{
#pragma unroll
    for (int u = 0; u < NSTEP; u++) {
        int ti = t + u - off;
        x[u] = (ti >= 0) ? __ldg(xp + (size_t)ti * NF) : 0.f;
        y[u] = __ldg(yp + (size_t)(t + u) * NF);
    }
}
// Unguarded prefetch (t >= 16 -> shifted index always in range).
__device__ __forceinline__ void prefetch_u(float (&x)[NSTEP], float (&y)[NSTEP],
                                           const float* __restrict__ xp,
                                           const float* __restrict__ yp,
                                           int t, int off)
{
#pragma unroll
    for (int u = 0; u < NSTEP; u++) {
        x[u] = __ldg(xp + (size_t)(t + u - off) * NF);
        y[u] = __ldg(yp + (size_t)(t + u) * NF);
    }
}

__device__ __forceinline__ void run_block(
    u64 (&W2)[8], u64 (&P)[8], u64 (&Q)[8],
    float& S, float& CC, float& xlast,
    const float (&xb)[NSTEP], const float (&yb)[NSTEP],
    float* __restrict__ ep, int t0, int h)
{
    float minv[NSTEP];
    float ccs[NPB];
    float xm1_0 = xlast;

    // ---- Prologue: local partial norms / cross-correlations (X-only) ----
    // Reads OLD ring slots (drops) before insertion; independent of W, so
    // the shuffles and MUFU.RCPs sit off the serial recursion path.
    u64 spp[NPB];
    float cpl[NPB];
    {
        float Sl = S, CCl = CC;
#pragma unroll
        for (int p = 0; p < NPB; p++) {
            float a, b, bq, cq;
            unpack2(P[p], a, b);   // (x'_{t-17}, x'_{t-16})
            unpack2(Q[p], bq, cq); // (x'_{t-16}, x'_{t-15})
            float xm1 = p ? xb[2 * p - 1] : xm1_0;
            float x0 = xb[2 * p], x1 = xb[2 * p + 1];
            Sl = fmaf(x0, x0, Sl);
            Sl = fmaf(-b, b, Sl);
            float s0 = Sl;
            Sl = fmaf(x1, x1, Sl);
            Sl = fmaf(-cq, cq, Sl);
            spp[p] = pack2(s0, Sl);
            CCl = fmaf(xm1, x0, CCl);
            CCl = fmaf(x0, x1, CCl);
            CCl = fmaf(-a, b, CCl);
            CCl = fmaf(-bq, cq, CCl);
            cpl[p] = CCl;
        }
        S = Sl; CC = CCl;
    }
    // Exchange partial norms, compute step sizes (both threads redundantly).
#pragma unroll
    for (int p = 0; p < NPB; p++) {
        u64 ss = fadd2(spp[p], shfl64(spp[p]));
        float s0, s1;
        unpack2(ss, s0, s1);
        minv[2 * p]     = __fdividef(MU, s0 + EPSV);
        minv[2 * p + 1] = __fdividef(MU, s1 + EPSV);
    }
    // Exchange partial cross-correlations.
#pragma unroll
    for (int p = 0; p < NPB; p += 2) {
        u64 cv = pack2(cpl[p], cpl[p + 1]);
        u64 cs = fadd2(cv, shfl64(cv));
        unpack2(cs, ccs[p], ccs[p + 1]);
    }
    xlast = xb[NSTEP - 1];

    // ---- Serial recursion: 2 steps per iteration ----
#pragma unroll
    for (int p = 0; p < NPB; p++) {
        float xm1 = p ? xb[2 * p - 1] : xm1_0;
        float x0 = xb[2 * p], x1 = xb[2 * p + 1];
        P[p] = pack2(xm1, x0);  // slot holds (x'_{t-1}, x'_t)
        Q[p] = pack2(x0, x1);   // slot holds (x'_t, x'_{t+1})

        // Half-dots over own 8 pair-slots: window pair i -> slot (p+1+i)&7.
        u64 a0 = 0, a1 = 0, a2 = 0, a3 = 0;
        u64 b0 = 0, b1 = 0, b2 = 0, b3 = 0;
#pragma unroll
        for (int i = 0; i < 8; i += 4) {
            a0 = ffma2(W2[i + 0], P[(p + 1 + i) & 7], a0);
            a1 = ffma2(W2[i + 1], P[(p + 2 + i) & 7], a1);
            a2 = ffma2(W2[i + 2], P[(p + 3 + i) & 7], a2);
            a3 = ffma2(W2[i + 3], P[(p + 4 + i) & 7], a3);
            b0 = ffma2(W2[i + 0], Q[(p + 1 + i) & 7], b0);
            b1 = ffma2(W2[i + 1], Q[(p + 2 + i) & 7], b1);
            b2 = ffma2(W2[i + 2], Q[(p + 3 + i) & 7], b2);
            b3 = ffma2(W2[i + 3], Q[(p + 4 + i) & 7], b3);
        }
        u64 ap = fadd2(fadd2(a0, a1), fadd2(a2, a3));
        u64 aq = fadd2(fadd2(b0, b1), fadd2(b2, b3));
        float plo, phi, qlo, qhi;
        unpack2(ap, plo, phi);
        unpack2(aq, qlo, qhi);
        // Sum halves across the lane pair with one 64-bit butterfly.
        u64 pq = pack2(plo + phi, qlo + qhi);
        u64 pqs = fadd2(pq, shfl64(pq));
        float pt, qt;
        unpack2(pqs, pt, qt);

        float e0 = yb[2 * p] - pt;
        float c0 = e0 * minv[2 * p];
        float e1 = fmaf(-c0, ccs[p], yb[2 * p + 1] - qt);
        float c1 = e1 * minv[2 * p + 1];

        if (h) {  // one writer per sequence
            ep[(size_t)(t0 + 2 * p) * NF] = e0;
            ep[(size_t)(t0 + 2 * p + 1) * NF] = e1;
        }

        u64 c0p = pack2(c0, c0);
        u64 c1p = pack2(c1, c1);
#pragma unroll
        for (int i = 0; i < 8; i++) {
            W2[i] = ffma2(c1p, Q[(p + 1 + i) & 7],
                          ffma2(c0p, P[(p + 1 + i) & 7], W2[i]));
        }
    }
}

__global__ void __launch_bounds__(128, 2)
nlms_kernel(const float* __restrict__ X, const float* __restrict__ Y,
            const float* __restrict__ Wp, float* __restrict__ out,
            int write_w)
{
    int gtid = blockIdx.x * blockDim.x + threadIdx.x;
    if (gtid >= NTHREAD) return;
    int h = gtid & 1;          // tap-half owner
    int seq = gtid >> 1;
    int b = seq / NF;
    int f = seq - b * NF;
    int off = 16 * (1 - h);    // time shift of this thread's x stream

    size_t base = (size_t)b * NT * NF + f;
    const float* xp = X + base;
    const float* yp = Y + base;
    float* ep = out + base;    // E_hat_mag at offset 0

    u64 W2[8], P[8], Q[8];
#pragma unroll
    for (int i = 0; i < 8; i++) {
        int j = 16 * h + 2 * i;
        float w0 = Wp[((size_t)b * NL + j) * NF + f];
        float w1 = Wp[((size_t)b * NL + j + 1) * NF + f];
        W2[i] = pack2(w0, w1);
        P[i] = 0;  // zero pad: window starts empty
        Q[i] = 0;
    }
    float S = 0.f, CC = 0.f, xlast = 0.f;

    float xA[NSTEP], yA[NSTEP], xB[NSTEP], yB[NSTEP];
    prefetch_g(xA, yA, xp, yp, 0, off);

    int t0 = 0;
    for (int bb = 0; bb < NDBL; bb++) {
        prefetch_u(xB, yB, xp, yp, t0 + NSTEP, off);
        run_block(W2, P, Q, S, CC, xlast, xA, yA, ep, t0, h);
        t0 += NSTEP;
        prefetch_u(xA, yA, xp, yp, t0 + NSTEP, off);  // last lands on block 124
        run_block(W2, P, Q, S, CC, xlast, xB, yB, ep, t0, h);
        t0 += NSTEP;
    }
    run_block(W2, P, Q, S, CC, xlast, xA, yA, ep, t0, h);  // t0 = 1984

    if (write_w) {
        float* wf = out + (size_t)NB * NT * NF;  // W_final after E
#pragma unroll
        for (int i = 0; i < 8; i++) {
            int j = 16 * h + 2 * i;
            float w0, w1;
            unpack2(W2[i], w0, w1);
            wf[((size_t)b * NL + j) * NF + f] = w0;
            wf[((size_t)b * NL + j + 1) * NF + f] = w1;
        }
    }
}

extern "C" void kernel_launch(void* const* d_in, const int* in_sizes, int n_in,
                              void* d_out, int out_size)
{
    const float* X  = (const float*)d_in[0];  // X_hat_mag [B,T,F]
    const float* Y  = (const float*)d_in[1];  // Y_mag     [B,T,F]
    const float* Wp = (const float*)d_in[2];  // W_prev    [B,L,F]
    float* out = (float*)d_out;

    long long need = (long long)NB * NT * NF + (long long)NB * NL * NF;
    int write_w = ((long long)out_size >= need) ? 1 : 0;

    // 32832 threads (1026 full warps), 128/block -> 257 blocks, one wave.
    nlms_kernel<<<257, 128>>>(X, Y, Wp, out, write_w);
}